// round 3
// baseline (speedup 1.0000x reference)
#include <cuda_runtime.h>
#include <math.h>

#define BB 1024
#define NN 32
#define DOBS 17
#define DACT 6
#define DIN 23
#define HH 256
#define NSTEPS 5
#define HSTRIDE 36   // padded row stride (words) for k-major tiles: 16B aligned, low-conflict

// Transposed W2 (column-major) for coalesced/vectorized FORWARD reads.
__device__ float g_W2T[2][HH * HH];

__global__ void transpose_w2(const float* __restrict__ w2a,
                             const float* __restrict__ w2b) {
    int j = blockIdx.x;   // 0..255
    int k = threadIdx.x;  // 0..255
    g_W2T[0][j * HH + k] = w2a[k * HH + j];
    g_W2T[1][j * HH + k] = w2b[k * HH + j];
}

// ---- packed f32x2 helpers (sm_103a) ----
__device__ __forceinline__ unsigned long long fma2(unsigned long long a,
                                                   unsigned long long b,
                                                   unsigned long long c) {
    unsigned long long d;
    asm("fma.rn.f32x2 %0, %1, %2, %3;" : "=l"(d) : "l"(a), "l"(b), "l"(c));
    return d;
}
__device__ __forceinline__ unsigned long long pack2(float x, float y) {
    unsigned long long r;
    asm("mov.b64 %0, {%1, %2};" : "=l"(r) : "f"(x), "f"(y));
    return r;
}
__device__ __forceinline__ void unpack2(unsigned long long v, float& lo, float& hi) {
    asm("mov.b64 {%0, %1}, %2;" : "=f"(lo), "=f"(hi) : "l"(v));
}

__global__ __launch_bounds__(256, 2) void svgd_kernel(
    const float* __restrict__ obs, const float* __restrict__ a0,
    const float* __restrict__ W1a, const float* __restrict__ B1a,
    const float* __restrict__ W2a, const float* __restrict__ B2a,
    const float* __restrict__ W3a, const float* __restrict__ B3a,
    const float* __restrict__ W1b, const float* __restrict__ B1b,
    const float* __restrict__ W2b, const float* __restrict__ B2b,
    const float* __restrict__ W3b, const float* __restrict__ B3b,
    float* __restrict__ out)
{
    // k-major activation tile: row k holds 32 n-values (padded stride 36).
    __shared__ __align__(16) float s_hT[HH * HSTRIDE];   // 36 KB (also sort scratch)
    __shared__ __align__(16) float s_xT[32 * 32];        // input k-major: row k, 32 n
    __shared__ float s_d2[NN * NN];
    __shared__ float s_K[NN * NN];
    __shared__ float s_q[2][NN];
    __shared__ __align__(16) float s_s[NN * 8];          // score, stride 8
    __shared__ float s_a[NN * 8];                        // actions, stride 8
    __shared__ float s_logp[NN];
    __shared__ float s_lpn[NN];
    __shared__ float s_red[8 * NN];
    __shared__ float s_gate[NN];

    const int b = blockIdx.x;
    const int tid = threadIdx.x;
    const int lane = tid & 31;
    const int warp = tid >> 5;

    // Load obs (k-major) + a0
    for (int idx = tid; idx < NN * DOBS; idx += 256) {
        int n = idx / DOBS, k = idx % DOBS;
        s_xT[k * 32 + n] = obs[(b * NN + n) * DOBS + k];
    }
    for (int idx = tid; idx < NN * DACT; idx += 256) {
        int n = idx / DACT, d = idx % DACT;
        s_a[n * 8 + d] = a0[(b * NN + n) * DACT + d];
    }
    if (tid < NN) s_logp[tid] = 0.0f;
    __syncthreads();
    if (tid < NN) {
        float ss = 0.0f;
        #pragma unroll
        for (int d = 0; d < DACT; d++) { float v = s_a[tid * 8 + d]; ss += v * v; }
        s_lpn[tid] = -3.0f * logf(6.283185307179586f * 0.3f) - (0.5f / 0.3f) * ss;
    }

    for (int step = 0; step < NSTEPS; ++step) {
        __syncthreads();
        for (int idx = tid; idx < NN * DACT; idx += 256) {
            int n = idx / DACT, d = idx % DACT;
            s_xT[(DOBS + d) * 32 + n] = s_a[n * 8 + d];
        }
        for (int idx = tid; idx < NN * 8; idx += 256) s_s[idx] = 0.0f;
        __syncthreads();

        unsigned m1[2], m2[2];

        // ================= forward both Q nets =================
        for (int net = 0; net < 2; ++net) {
            const float* W1 = net ? W1b : W1a;
            const float* B1 = net ? B1b : B1a;
            const float* B2 = net ? B2b : B2a;
            const float* W3 = net ? W3b : W3a;
            const float* B3 = net ? B3b : B3a;
            const float* W2T = g_W2T[net] + tid * HH;

            // ---- layer1 (packed over n-pairs): thread j = hidden unit j ----
            float c[DIN];
            #pragma unroll
            for (int k = 0; k < DIN; k++) c[k] = W1[k * HH + tid];
            float bb1 = B1[tid];

            unsigned long long acc[16];
            #pragma unroll
            for (int p = 0; p < 16; p++) acc[p] = 0ull;
            #pragma unroll
            for (int k = 0; k < DIN; k++) {
                unsigned long long wp = pack2(c[k], c[k]);
                const ulonglong2* xr = (const ulonglong2*)&s_xT[k * 32];
                #pragma unroll
                for (int p = 0; p < 8; p++) {
                    ulonglong2 xv = xr[p];
                    acc[2 * p]     = fma2(xv.x, wp, acc[2 * p]);
                    acc[2 * p + 1] = fma2(xv.y, wp, acc[2 * p + 1]);
                }
            }
            unsigned mm1 = 0;
            float* hrow = &s_hT[tid * HSTRIDE];
            #pragma unroll
            for (int p = 0; p < 8; p++) {
                float z0, z1, z2, z3;
                unpack2(acc[2 * p], z0, z1);
                unpack2(acc[2 * p + 1], z2, z3);
                z0 += bb1; z1 += bb1; z2 += bb1; z3 += bb1;
                int n0 = 4 * p;
                if (z0 > 0.0f) mm1 |= (1u << (n0 + 0)); else z0 = 0.0f;
                if (z1 > 0.0f) mm1 |= (1u << (n0 + 1)); else z1 = 0.0f;
                if (z2 > 0.0f) mm1 |= (1u << (n0 + 2)); else z2 = 0.0f;
                if (z3 > 0.0f) mm1 |= (1u << (n0 + 3)); else z3 = 0.0f;
                *(float4*)&hrow[n0] = make_float4(z0, z1, z2, z3);
            }
            m1[net] = mm1;
            __syncthreads();

            // ---- layer2 fwd (packed): acc[n] = sum_k h[k][n] * W2T[tid][k] ----
            #pragma unroll
            for (int p = 0; p < 16; p++) acc[p] = 0ull;
            for (int k4 = 0; k4 < HH; k4 += 4) {
                float4 w4 = *(const float4*)&W2T[k4];
                #pragma unroll
                for (int kk = 0; kk < 4; kk++) {
                    float wk = (kk == 0) ? w4.x : (kk == 1) ? w4.y : (kk == 2) ? w4.z : w4.w;
                    unsigned long long wp = pack2(wk, wk);
                    const ulonglong2* hr = (const ulonglong2*)&s_hT[(k4 + kk) * HSTRIDE];
                    #pragma unroll
                    for (int p = 0; p < 8; p++) {
                        ulonglong2 hv = hr[p];
                        acc[2 * p]     = fma2(hv.x, wp, acc[2 * p]);
                        acc[2 * p + 1] = fma2(hv.y, wp, acc[2 * p + 1]);
                    }
                }
            }
            float bb2 = B2[tid], w3v = W3[tid];
            unsigned mm2 = 0;
            float vals[NN];
            #pragma unroll
            for (int p = 0; p < 16; p++) {
                float z0, z1;
                unpack2(acc[p], z0, z1);
                z0 += bb2; z1 += bb2;
                int n0 = 2 * p;
                if (z0 > 0.0f) { mm2 |= (1u << (n0 + 0)); vals[n0 + 0] = z0 * w3v; } else vals[n0 + 0] = 0.0f;
                if (z1 > 0.0f) { mm2 |= (1u << (n0 + 1)); vals[n0 + 1] = z1 * w3v; } else vals[n0 + 1] = 0.0f;
            }
            m2[net] = mm2;

            // block-reduce vals[n] -> q[n]
            #pragma unroll
            for (int n = 0; n < NN; n++) {
                float v = vals[n];
                v += __shfl_xor_sync(0xffffffffu, v, 16);
                v += __shfl_xor_sync(0xffffffffu, v, 8);
                v += __shfl_xor_sync(0xffffffffu, v, 4);
                v += __shfl_xor_sync(0xffffffffu, v, 2);
                v += __shfl_xor_sync(0xffffffffu, v, 1);
                if (lane == 0) s_red[warp * NN + n] = v;
            }
            __syncthreads();
            if (tid < NN) {
                float q = B3[0];
                #pragma unroll
                for (int w = 0; w < 8; w++) q += s_red[w * NN + tid];
                s_q[net][tid] = q;
            }
            __syncthreads();
        }

        if (tid < NN) s_gate[tid] = (s_q[0][tid] <= s_q[1][tid]) ? 1.0f : 0.0f;
        __syncthreads();

        // ================= backward both Q nets (input grad only) =================
        for (int net = 0; net < 2; ++net) {
            const float* W1 = net ? W1b : W1a;
            const float* W2 = net ? W2b : W2a;
            const float* W3 = net ? W3b : W3a;
            float w3v = W3[tid];
            unsigned mm2 = m2[net], mm1 = m1[net];

            // dh2_T[j][n] = gate[n]*W3[j]*mask2   (j-major, thread tid = j)
            {
                float* row = &s_hT[tid * HSTRIDE];
                #pragma unroll
                for (int p = 0; p < 8; p++) {
                    float v[4];
                    #pragma unroll
                    for (int q = 0; q < 4; q++) {
                        int n = 4 * p + q;
                        float g = net ? (1.0f - s_gate[n]) : s_gate[n];
                        v[q] = ((mm2 >> n) & 1u) ? g * w3v : 0.0f;
                    }
                    *(float4*)&row[4 * p] = make_float4(v[0], v[1], v[2], v[3]);
                }
            }
            __syncthreads();

            // dh1[n][tid] = sum_j dh2_T[j][n] * W2[tid][j]  (W2 row j-contiguous)
            unsigned long long acc[16];
            #pragma unroll
            for (int p = 0; p < 16; p++) acc[p] = 0ull;
            const float* w2r = W2 + tid * HH;
            for (int j4 = 0; j4 < HH; j4 += 4) {
                float4 w4 = *(const float4*)&w2r[j4];
                #pragma unroll
                for (int jj = 0; jj < 4; jj++) {
                    float wk = (jj == 0) ? w4.x : (jj == 1) ? w4.y : (jj == 2) ? w4.z : w4.w;
                    unsigned long long wp = pack2(wk, wk);
                    const ulonglong2* dr = (const ulonglong2*)&s_hT[(j4 + jj) * HSTRIDE];
                    #pragma unroll
                    for (int p = 0; p < 8; p++) {
                        ulonglong2 dv = dr[p];
                        acc[2 * p]     = fma2(dv.x, wp, acc[2 * p]);
                        acc[2 * p + 1] = fma2(dv.y, wp, acc[2 * p + 1]);
                    }
                }
            }
            __syncthreads();  // all dh2 reads done before overwrite

            // apply relu mask1, store dh1 k-major
            {
                float* row = &s_hT[tid * HSTRIDE];
                #pragma unroll
                for (int p = 0; p < 8; p++) {
                    float z0, z1, z2, z3;
                    unpack2(acc[2 * p], z0, z1);
                    unpack2(acc[2 * p + 1], z2, z3);
                    int n0 = 4 * p;
                    if (!((mm1 >> (n0 + 0)) & 1u)) z0 = 0.0f;
                    if (!((mm1 >> (n0 + 1)) & 1u)) z1 = 0.0f;
                    if (!((mm1 >> (n0 + 2)) & 1u)) z2 = 0.0f;
                    if (!((mm1 >> (n0 + 3)) & 1u)) z3 = 0.0f;
                    *(float4*)&row[n0] = make_float4(z0, z1, z2, z3);
                }
            }
            __syncthreads();

            // da[n][d] = sum_k dh1_T[k][n] * W1[17+d][k]  -> accumulate into s_s
            if (tid < NN * DACT) {
                int n = tid / DACT, d = tid % DACT;
                const float* w1r = W1 + (DOBS + d) * HH;
                float sum = 0.0f;
                for (int k4 = 0; k4 < HH; k4 += 4) {
                    float4 w4 = *(const float4*)&w1r[k4];
                    sum += s_hT[(k4 + 0) * HSTRIDE + n] * w4.x
                         + s_hT[(k4 + 1) * HSTRIDE + n] * w4.y
                         + s_hT[(k4 + 2) * HSTRIDE + n] * w4.z
                         + s_hT[(k4 + 3) * HSTRIDE + n] * w4.w;
                }
                s_s[n * 8 + d] += sum;
            }
            __syncthreads();
        }

        // ================= SVGD update =================
        for (int p = tid; p < NN * NN; p += 256) {
            int i = p >> 5, j = p & 31;
            float ds = 0.0f;
            #pragma unroll
            for (int d = 0; d < DACT; d++) {
                float df = s_a[i * 8 + d] - s_a[j * 8 + d];
                ds += df * df;
            }
            s_d2[p] = ds;
            s_hT[p] = ds;  // sort copy (h data dead here)
        }
        __syncthreads();

        // bitonic sort of 1024 values (exact median)
        for (int ks = 2; ks <= NN * NN; ks <<= 1) {
            for (int jj = ks >> 1; jj > 0; jj >>= 1) {
                #pragma unroll
                for (int e = 0; e < 4; e++) {
                    int idx = (e << 8) | tid;
                    int ixj = idx ^ jj;
                    if (ixj > idx) {
                        float va = s_hT[idx], vb = s_hT[ixj];
                        bool up = ((idx & ks) == 0);
                        if ((va > vb) == up) { s_hT[idx] = vb; s_hT[ixj] = va; }
                    }
                }
                __syncthreads();
            }
        }

        float med = 0.5f * (s_hT[511] + s_hT[512]);
        float hm = med / logf(33.0f);
        float gamma = 1.0f / (2.0f * hm + 1e-8f);
        for (int p = tid; p < NN * NN; p += 256)
            s_K[p] = expf(-gamma * s_d2[p]);
        __syncthreads();

        float anew[DACT];
        float lpdelta = 0.0f;
        if (tid < NN) {
            int i = tid;
            float ai[DACT];
            #pragma unroll
            for (int d = 0; d < DACT; d++) ai[d] = s_a[i * 8 + d];
            float ph[DACT] = {0, 0, 0, 0, 0, 0};
            float t1 = 0.0f, t2s = 0.0f;
            for (int j = 0; j < NN; j++) {
                float Kij = s_K[i * 32 + j];
                float dot = 0.0f;
                #pragma unroll
                for (int d = 0; d < DACT; d++) {
                    float df = ai[d] - s_a[j * 8 + d];
                    float sj = s_s[j * 8 + d];
                    dot += df * sj;
                    ph[d] += Kij * sj + 2.0f * gamma * Kij * df;
                }
                t1 += -2.0f * gamma * Kij * dot;
                float I = (i == j) ? 1.0f : 0.0f;
                t2s += 2.0f * gamma * Kij * s_d2[i * 32 + j] - 6.0f * (Kij - I);
            }
            t1 *= (1.0f / 31.0f);
            float t2 = -2.0f * gamma * t2s * (1.0f / 31.0f);
            lpdelta = 0.05f * (t1 + t2);
            #pragma unroll
            for (int d = 0; d < DACT; d++)
                anew[d] = ai[d] + 0.05f * ph[d] * (1.0f / 32.0f);
        }
        __syncthreads();
        if (tid < NN) {
            s_logp[tid] -= lpdelta;
            #pragma unroll
            for (int d = 0; d < DACT; d++) s_a[tid * 8 + d] = anew[d];
        }
        __syncthreads();
    }

    // ================= finalize =================
    __syncthreads();
    if (tid < NN) {
        int n = tid;
        float lpt = 0.0f;
        #pragma unroll
        for (int d = 0; d < DACT; d++) {
            float av = s_a[n * 8 + d];
            float x = -2.0f * av;
            float sp = (x > 0.0f) ? (x + log1pf(expf(-x))) : log1pf(expf(x));
            lpt += -2.0f * (0.6931471805599453f - av - sp);
            out[(b * NN + n) * DACT + d] = tanhf(av);
        }
        s_red[n] = s_lpn[n] + s_logp[n] + lpt;
    }
    __syncthreads();
    if (tid == 0) {
        float m = 0.0f;
        for (int n = 0; n < NN; n++) m += s_red[n];
        out[BB * NN * DACT + b] = m * (1.0f / 32.0f);
    }
}

extern "C" void kernel_launch(void* const* d_in, const int* in_sizes, int n_in,
                              void* d_out, int out_size) {
    const float* obs  = (const float*)d_in[0];
    const float* a0   = (const float*)d_in[1];
    const float* q1W1 = (const float*)d_in[2];
    const float* q1b1 = (const float*)d_in[3];
    const float* q1W2 = (const float*)d_in[4];
    const float* q1b2 = (const float*)d_in[5];
    const float* q1W3 = (const float*)d_in[6];
    const float* q1b3 = (const float*)d_in[7];
    const float* q2W1 = (const float*)d_in[8];
    const float* q2b1 = (const float*)d_in[9];
    const float* q2W2 = (const float*)d_in[10];
    const float* q2b2 = (const float*)d_in[11];
    const float* q2W3 = (const float*)d_in[12];
    const float* q2b3 = (const float*)d_in[13];
    float* out = (float*)d_out;

    transpose_w2<<<HH, HH>>>(q1W2, q2W2);
    svgd_kernel<<<BB, 256>>>(obs, a0,
                             q1W1, q1b1, q1W2, q1b2, q1W3, q1b3,
                             q2W1, q2b1, q2W2, q2b2, q2W3, q2b3,
                             out);
}